// round 3
// baseline (speedup 1.0000x reference)
#include <cuda_runtime.h>

// Problem constants
#define BB 16
#define NND 1024
#define UU 64
#define NN2 (NND*NND)
#define TAUV 0.5f
#define EPSV 1e-10f

// ---------------- scratch (device globals; no allocations allowed) ----------------
__device__ float g_adj[(size_t)BB*NND*NND];   // 64 MB
__device__ float g_rowsum[BB*NND];
__device__ float g_colpart[4*BB*NND];
__device__ float g_s0[BB*NND];
__device__ float g_s1[BB*NND];
__device__ float g_X[BB*NND*128];             // [x | h]
__device__ float g_G0[BB*NND*128];            // adj  @ X
__device__ float g_G1[BB*NND*128];            // adjT @ X
__device__ float g_Q[BB*NND*64];              // r * h
__device__ float g_Ubuf[BB*NND*64];           // u gate
__device__ float g_H0[BB*NND*64];             // adj  @ Q
__device__ float g_H1[BB*NND*64];             // adjT @ Q
__device__ float g_Phi[BB*NND*384];           // diffusion features (reused both phases)
__device__ float g_WT[384*128];               // [Wx0+Wx1 | W0a | W1a] transposed (k-major)
__device__ float g_bv[128];
__device__ float g_WcT[384*64];
__device__ float g_bc[64];

// ---------------- packed f32x2 helpers ----------------
__device__ __forceinline__ unsigned long long fma2(unsigned long long a,
                                                   unsigned long long b,
                                                   unsigned long long c) {
    unsigned long long d;
    asm("fma.rn.f32x2 %0, %1, %2, %3;" : "=l"(d) : "l"(a), "l"(b), "l"(c));
    return d;
}
__device__ __forceinline__ unsigned long long pk(float lo, float hi) {
    unsigned long long r;
    asm("mov.b64 %0, {%1, %2};" : "=l"(r) : "f"(lo), "f"(hi));
    return r;
}
__device__ __forceinline__ float2 unpk(unsigned long long v) {
    float2 r;
    asm("mov.b64 {%0, %1}, %2;" : "=f"(r.x), "=f"(r.y) : "l"(v));
    return r;
}

// ---------------- 1. weight preprocessing ----------------
// _diffusion stacks [x, Ax, Ax]  =>  effective weights:
//   Wx[o,c] = W[o,3c],  Wa[o,c] = W[o,3c+1] + W[o,3c+2]
// Feature layout of Phi: [X(128) | A0X(128) | A1X(128)]  (matches builds below)
__global__ void prep_weights_kernel(const float* __restrict__ W0, const float* __restrict__ b0,
                                    const float* __restrict__ W1, const float* __restrict__ b1,
                                    const float* __restrict__ Wc0, const float* __restrict__ bc0,
                                    const float* __restrict__ Wc1, const float* __restrict__ bc1) {
    int t = blockIdx.x * blockDim.x + threadIdx.x;
    if (t < 128 * 128) {
        int c = t >> 7, o = t & 127;
        g_WT[c * 128 + o]         = W0[o * 384 + 3 * c]     + W1[o * 384 + 3 * c];
        g_WT[(128 + c) * 128 + o] = W0[o * 384 + 3 * c + 1] + W0[o * 384 + 3 * c + 2];
        g_WT[(256 + c) * 128 + o] = W1[o * 384 + 3 * c + 1] + W1[o * 384 + 3 * c + 2];
    }
    if (t < 128) g_bv[t] = b0[t] + b1[t];
    if (t < 128 * 64) {
        int c = t >> 6, o = t & 63;
        g_WcT[c * 64 + o]         = Wc0[o * 384 + 3 * c]     + Wc1[o * 384 + 3 * c];
        g_WcT[(128 + c) * 64 + o] = Wc0[o * 384 + 3 * c + 1] + Wc0[o * 384 + 3 * c + 2];
        g_WcT[(256 + c) * 64 + o] = Wc1[o * 384 + 3 * c + 1] + Wc1[o * 384 + 3 * c + 2];
    }
    if (t < 64) g_bc[t] = bc0[t] + bc1[t];
}

// ---------------- 2. adjacency (gumbel softmax over last dim of 2) + row sums ----------------
__global__ void adj_kernel(const float2* __restrict__ lg, const float2* __restrict__ un) {
    int i = blockIdx.x, b = blockIdx.y;
    size_t base = (size_t)b * NN2 + (size_t)i * NND;
    float rsum = 0.f;
    for (int j = threadIdx.x; j < NND; j += 256) {
        float2 l = lg[base + j];
        float2 u = un[base + j];
        float n0 = -logf(EPSV - logf(u.x + EPSV));
        float n1 = -logf(EPSV - logf(u.y + EPSV));
        float z  = ((l.x + n0) - (l.y + n1)) * (1.0f / TAUV);
        float p  = 1.0f / (1.0f + expf(-z));   // == softmax(...)[0]
        g_adj[base + j] = p;
        rsum += p;
    }
    __shared__ float red[256];
    red[threadIdx.x] = rsum;
    __syncthreads();
    for (int s = 128; s > 0; s >>= 1) {
        if (threadIdx.x < s) red[threadIdx.x] += red[threadIdx.x + s];
        __syncthreads();
    }
    if (threadIdx.x == 0) g_rowsum[b * NND + i] = red[0];
}

// ---------------- 3. deterministic column sums (partial over 4 row chunks) ----------------
__global__ void colsum_kernel() {
    int j = blockIdx.x * 256 + threadIdx.x;   // gridDim.x = 4
    int b = blockIdx.y;
    int ch = blockIdx.z;                       // 4 chunks of 256 rows
    size_t base = (size_t)b * NN2 + (size_t)(ch * 256) * NND + j;
    float acc = 0.f;
    #pragma unroll 8
    for (int i = 0; i < 256; i++) acc += g_adj[base + (size_t)i * NND];
    g_colpart[ch * (BB * NND) + b * NND + j] = acc;
}

// ---------------- 4. scales: note reference's column-sum scaling quirk ----------------
__global__ void scales_kernel() {
    int m = blockIdx.x * 256 + threadIdx.x;    // 16384
    float cs = g_colpart[m] + g_colpart[16384 + m] + g_colpart[2 * 16384 + m] + g_colpart[3 * 16384 + m];
    g_s0[m] = 1.0f / (cs + 1.0f);              // A0 rows scaled by 1/(colsum+1)
    g_s1[m] = 1.0f / (g_rowsum[m] + 1.0f);     // A1 rows scaled by 1/(rowsum+1)
}

// ---------------- 5. X = [x | h] ----------------
__global__ void buildX_kernel(const float* __restrict__ inp, const float* __restrict__ hx) {
    int idx = blockIdx.x * 256 + threadIdx.x;  // 16384*128
    int m = idx >> 7, c = idx & 127;
    g_X[idx] = (c < 64) ? inp[m * 64 + c] : hx[m * 64 + (c - 64)];
}

// ---------------- 6. batched GEMM: Y = adj @ X (z=0) and adjT @ X (z=1) ----------------
template <int NC>
__global__ void __launch_bounds__(256)
adj_gemm_kernel() {
    constexpr int TM  = (NC == 128) ? 8 : 4;
    constexpr int NTX = NC / 8;
    const float* Xin = (NC == 128) ? g_X : g_Q;
    float* Y = (blockIdx.z == 0) ? ((NC == 128) ? g_G0 : g_H0)
                                 : ((NC == 128) ? g_G1 : g_H1);
    const bool trans = (blockIdx.z == 1);
    const int b  = blockIdx.y;
    const int i0 = blockIdx.x * 128;
    const float* Ab = g_adj + (size_t)b * NN2;
    const float* Xb = Xin + (size_t)b * NND * NC;

    __shared__ float As[16][128];
    __shared__ float Xs[16][NC];

    const int t  = threadIdx.x;
    const int tx = t % NTX, ty = t / NTX;

    unsigned long long acc[TM][4];
    #pragma unroll
    for (int ii = 0; ii < TM; ii++)
        #pragma unroll
        for (int q = 0; q < 4; q++) acc[ii][q] = 0ULL;

    for (int k0 = 0; k0 < NND; k0 += 16) {
        if (!trans) {
            int iA = t >> 2;
            int kq = (t & 3) * 4;
            #pragma unroll
            for (int h = 0; h < 2; h++) {
                int ii = iA + h * 64;
                const float4 v = *reinterpret_cast<const float4*>(Ab + (size_t)(i0 + ii) * NND + k0 + kq);
                As[kq + 0][ii] = v.x; As[kq + 1][ii] = v.y;
                As[kq + 2][ii] = v.z; As[kq + 3][ii] = v.w;
            }
        } else {
            int i4 = (t & 31) * 4;
            int k  = t >> 5;
            #pragma unroll
            for (int h = 0; h < 2; h++) {
                int kk2 = k + h * 8;
                const float4 v = *reinterpret_cast<const float4*>(Ab + (size_t)(k0 + kk2) * NND + i0 + i4);
                *reinterpret_cast<float4*>(&As[kk2][i4]) = v;
            }
        }
        if (NC == 128) {
            int j4 = (t & 31) * 4;
            int k  = t >> 5;
            #pragma unroll
            for (int h = 0; h < 2; h++) {
                int kk2 = k + h * 8;
                *reinterpret_cast<float4*>(&Xs[kk2][j4]) =
                    *reinterpret_cast<const float4*>(Xb + (size_t)(k0 + kk2) * NC + j4);
            }
        } else {
            int j4 = (t & 15) * 4;
            int k  = t >> 4;
            *reinterpret_cast<float4*>(&Xs[k][j4]) =
                *reinterpret_cast<const float4*>(Xb + (size_t)(k0 + k) * NC + j4);
        }
        __syncthreads();
        #pragma unroll
        for (int kk = 0; kk < 16; kk++) {
            float4 b0v = *reinterpret_cast<const float4*>(&Xs[kk][tx * 8]);
            float4 b1v = *reinterpret_cast<const float4*>(&Xs[kk][tx * 8 + 4]);
            unsigned long long bp0 = pk(b0v.x, b0v.y), bp1 = pk(b0v.z, b0v.w);
            unsigned long long bp2 = pk(b1v.x, b1v.y), bp3 = pk(b1v.z, b1v.w);
            #pragma unroll
            for (int ii = 0; ii < TM; ii++) {
                float a = As[kk][ty * TM + ii];
                unsigned long long ad = pk(a, a);
                acc[ii][0] = fma2(ad, bp0, acc[ii][0]);
                acc[ii][1] = fma2(ad, bp1, acc[ii][1]);
                acc[ii][2] = fma2(ad, bp2, acc[ii][2]);
                acc[ii][3] = fma2(ad, bp3, acc[ii][3]);
            }
        }
        __syncthreads();
    }
    #pragma unroll
    for (int ii = 0; ii < TM; ii++) {
        int row = i0 + ty * TM + ii;
        float* yp = Y + ((size_t)b * NND + row) * NC + tx * 8;
        #pragma unroll
        for (int q = 0; q < 4; q++) {
            float2 v = unpk(acc[ii][q]);
            *reinterpret_cast<float2*>(yp + q * 2) = v;
        }
    }
}

// ---------------- 7. diffusion-feature builds ----------------
// (adj+I)@X = G + X, scaled per-row.
__global__ void buildPhi1_kernel() {
    int idx = blockIdx.x * 256 + threadIdx.x;   // 16384*384
    int m = idx / 384;
    int k = idx - m * 384;
    float v;
    if (k < 128)      v = g_X[m * 128 + k];
    else if (k < 256) { int c = k - 128; v = g_s0[m] * (g_G0[m * 128 + c] + g_X[m * 128 + c]); }
    else              { int c = k - 256; v = g_s1[m] * (g_G1[m * 128 + c] + g_X[m * 128 + c]); }
    g_Phi[idx] = v;
}

__global__ void buildPhi2_kernel() {
    int idx = blockIdx.x * 256 + threadIdx.x;
    int m = idx / 384;
    int k = idx - m * 384;
    float v;
    if (k < 64)       v = g_X[m * 128 + k];
    else if (k < 128) v = g_Q[m * 64 + (k - 64)];
    else if (k < 192) { int c = k - 128; v = g_s0[m] * (g_G0[m * 128 + c] + g_X[m * 128 + c]); }
    else if (k < 256) { int c = k - 192; v = g_s0[m] * (g_H0[m * 64 + c] + g_Q[m * 64 + c]); }
    else if (k < 320) { int c = k - 256; v = g_s1[m] * (g_G1[m * 128 + c] + g_X[m * 128 + c]); }
    else              { int c = k - 320; v = g_s1[m] * (g_H1[m * 64 + c] + g_Q[m * 64 + c]); }
    g_Phi[idx] = v;
}

// ---------------- 8. FC GEMM (Phi @ W^T) with fused epilogues ----------------
// MODE 1: value=sigmoid(.); r -> Q=r*h, u -> Ubuf.   MODE 2: c=tanh(.); out=u*h+(1-u)*c
template <int NC, int MODE>
__global__ void __launch_bounds__(256)
fc_gemm_kernel(const float* __restrict__ hx, float* __restrict__ out) {
    constexpr int TM  = (NC == 128) ? 8 : 4;
    constexpr int NTX = NC / 8;
    const float* Wt = (NC == 128) ? g_WT : g_WcT;
    const int m0 = blockIdx.x * 128;

    __shared__ float As[16][128];
    __shared__ float Ws[16][NC];

    const int t  = threadIdx.x;
    const int tx = t % NTX, ty = t / NTX;

    unsigned long long acc[TM][4];
    #pragma unroll
    for (int ii = 0; ii < TM; ii++)
        #pragma unroll
        for (int q = 0; q < 4; q++) acc[ii][q] = 0ULL;

    for (int k0 = 0; k0 < 384; k0 += 16) {
        {
            int iA = t >> 2;
            int kq = (t & 3) * 4;
            #pragma unroll
            for (int h = 0; h < 2; h++) {
                int ii = iA + h * 64;
                const float4 v = *reinterpret_cast<const float4*>(&g_Phi[(size_t)(m0 + ii) * 384 + k0 + kq]);
                As[kq + 0][ii] = v.x; As[kq + 1][ii] = v.y;
                As[kq + 2][ii] = v.z; As[kq + 3][ii] = v.w;
            }
        }
        if (NC == 128) {
            int j4 = (t & 31) * 4;
            int k  = t >> 5;
            #pragma unroll
            for (int h = 0; h < 2; h++) {
                int kk2 = k + h * 8;
                *reinterpret_cast<float4*>(&Ws[kk2][j4]) =
                    *reinterpret_cast<const float4*>(&Wt[(k0 + kk2) * NC + j4]);
            }
        } else {
            int j4 = (t & 15) * 4;
            int k  = t >> 4;
            *reinterpret_cast<float4*>(&Ws[k][j4]) =
                *reinterpret_cast<const float4*>(&Wt[(k0 + k) * NC + j4]);
        }
        __syncthreads();
        #pragma unroll
        for (int kk = 0; kk < 16; kk++) {
            float4 b0v = *reinterpret_cast<const float4*>(&Ws[kk][tx * 8]);
            float4 b1v = *reinterpret_cast<const float4*>(&Ws[kk][tx * 8 + 4]);
            unsigned long long bp0 = pk(b0v.x, b0v.y), bp1 = pk(b0v.z, b0v.w);
            unsigned long long bp2 = pk(b1v.x, b1v.y), bp3 = pk(b1v.z, b1v.w);
            #pragma unroll
            for (int ii = 0; ii < TM; ii++) {
                float a = As[kk][ty * TM + ii];
                unsigned long long ad = pk(a, a);
                acc[ii][0] = fma2(ad, bp0, acc[ii][0]);
                acc[ii][1] = fma2(ad, bp1, acc[ii][1]);
                acc[ii][2] = fma2(ad, bp2, acc[ii][2]);
                acc[ii][3] = fma2(ad, bp3, acc[ii][3]);
            }
        }
        __syncthreads();
    }
    #pragma unroll
    for (int ii = 0; ii < TM; ii++) {
        int m = m0 + ty * TM + ii;
        #pragma unroll
        for (int q = 0; q < 4; q++) {
            float2 v = unpk(acc[ii][q]);
            #pragma unroll
            for (int r = 0; r < 2; r++) {
                int o = tx * 8 + q * 2 + r;
                float val = (r == 0) ? v.x : v.y;
                if (MODE == 1) {
                    float y = val + g_bv[o];
                    float s = 1.0f / (1.0f + expf(-y));
                    if (o < 64) g_Q[m * 64 + o] = s * hx[m * 64 + o];       // r * h
                    else        g_Ubuf[m * 64 + (o - 64)] = s;              // u
                } else {
                    float y  = val + g_bc[o];
                    float cc = tanhf(y);
                    float u  = g_Ubuf[m * 64 + o];
                    float h  = hx[m * 64 + o];
                    out[m * 64 + o] = u * h + (1.0f - u) * cc;
                }
            }
        }
    }
}

// ---------------- launch ----------------
extern "C" void kernel_launch(void* const* d_in, const int* in_sizes, int n_in,
                              void* d_out, int out_size) {
    (void)in_sizes; (void)n_in; (void)out_size;
    const float* logits = (const float*)d_in[0];
    const float* unoise = (const float*)d_in[1];
    const float* inputs = (const float*)d_in[2];
    const float* hx     = (const float*)d_in[3];
    const float* W0  = (const float*)d_in[4];
    const float* b0  = (const float*)d_in[5];
    const float* W1  = (const float*)d_in[6];
    const float* b1  = (const float*)d_in[7];
    const float* Wc0 = (const float*)d_in[8];
    const float* bc0 = (const float*)d_in[9];
    const float* Wc1 = (const float*)d_in[10];
    const float* bc1 = (const float*)d_in[11];
    float* out = (float*)d_out;

    prep_weights_kernel<<<64, 256>>>(W0, b0, W1, b1, Wc0, bc0, Wc1, bc1);
    adj_kernel<<<dim3(NND, BB), 256>>>((const float2*)logits, (const float2*)unoise);
    colsum_kernel<<<dim3(4, BB, 4), 256>>>();
    scales_kernel<<<64, 256>>>();
    buildX_kernel<<<(BB * NND * 128) / 256, 256>>>(inputs, hx);
    adj_gemm_kernel<128><<<dim3(8, BB, 2), 256>>>();            // G0 = adj@X, G1 = adjT@X
    buildPhi1_kernel<<<(BB * NND * 384) / 256, 256>>>();
    fc_gemm_kernel<128, 1><<<dim3(128), 256>>>(hx, out);        // value, r*h, u
    adj_gemm_kernel<64><<<dim3(8, BB, 2), 256>>>();             // H0 = adj@Q, H1 = adjT@Q
    buildPhi2_kernel<<<(BB * NND * 384) / 256, 256>>>();
    fc_gemm_kernel<64, 2><<<dim3(128), 256>>>(hx, out);         // c, new_state
}

// round 6
// speedup vs baseline: 1.1926x; 1.1926x over previous
#include <cuda_runtime.h>
#include <mma.h>
using namespace nvcuda;

// Problem constants
#define BB 16
#define NND 1024
#define UU 64
#define NN2 (NND*NND)
#define TAUV 0.5f
#define EPSV 1e-10f

// ---------------- scratch (device globals; no allocations allowed) ----------------
__device__ float g_adj[(size_t)BB*NND*NND];   // 64 MB
__device__ float g_rowsum[BB*NND];
__device__ float g_colpart[4*BB*NND];
__device__ float g_s0[BB*NND];
__device__ float g_s1[BB*NND];
__device__ float g_X[BB*NND*128];             // [x | h]
__device__ float g_G0[BB*NND*128];            // adj  @ X
__device__ float g_G1[BB*NND*128];            // adjT @ X
__device__ float g_Q[BB*NND*64];              // r * h
__device__ float g_Ubuf[BB*NND*64];           // u gate
__device__ float g_H0[BB*NND*64];             // adj  @ Q
__device__ float g_H1[BB*NND*64];             // adjT @ Q
__device__ float g_Phi[BB*NND*384];           // diffusion features (reused both phases)
__device__ float g_WT[384*128];               // [Wx0+Wx1 | W0a | W1a] transposed (k-major)
__device__ float g_bv[128];
__device__ float g_WcT[384*64];
__device__ float g_bc[64];

// ---------------- packed f32x2 helpers (fc_gemm path) ----------------
__device__ __forceinline__ unsigned long long fma2(unsigned long long a,
                                                   unsigned long long b,
                                                   unsigned long long c) {
    unsigned long long d;
    asm("fma.rn.f32x2 %0, %1, %2, %3;" : "=l"(d) : "l"(a), "l"(b), "l"(c));
    return d;
}
__device__ __forceinline__ unsigned long long pk(float lo, float hi) {
    unsigned long long r;
    asm("mov.b64 %0, {%1, %2};" : "=l"(r) : "f"(lo), "f"(hi));
    return r;
}
__device__ __forceinline__ float2 unpk(unsigned long long v) {
    float2 r;
    asm("mov.b64 {%0, %1}, %2;" : "=f"(r.x), "=f"(r.y) : "l"(v));
    return r;
}

// ---------------- 1. weight preprocessing ----------------
// _diffusion stacks [x, Ax, Ax]  =>  effective weights:
//   Wx[o,c] = W[o,3c],  Wa[o,c] = W[o,3c+1] + W[o,3c+2]
__global__ void prep_weights_kernel(const float* __restrict__ W0, const float* __restrict__ b0,
                                    const float* __restrict__ W1, const float* __restrict__ b1,
                                    const float* __restrict__ Wc0, const float* __restrict__ bc0,
                                    const float* __restrict__ Wc1, const float* __restrict__ bc1) {
    int t = blockIdx.x * blockDim.x + threadIdx.x;
    if (t < 128 * 128) {
        int c = t >> 7, o = t & 127;
        g_WT[c * 128 + o]         = W0[o * 384 + 3 * c]     + W1[o * 384 + 3 * c];
        g_WT[(128 + c) * 128 + o] = W0[o * 384 + 3 * c + 1] + W0[o * 384 + 3 * c + 2];
        g_WT[(256 + c) * 128 + o] = W1[o * 384 + 3 * c + 1] + W1[o * 384 + 3 * c + 2];
    }
    if (t < 128) g_bv[t] = b0[t] + b1[t];
    if (t < 128 * 64) {
        int c = t >> 6, o = t & 63;
        g_WcT[c * 64 + o]         = Wc0[o * 384 + 3 * c]     + Wc1[o * 384 + 3 * c];
        g_WcT[(128 + c) * 64 + o] = Wc0[o * 384 + 3 * c + 1] + Wc0[o * 384 + 3 * c + 2];
        g_WcT[(256 + c) * 64 + o] = Wc1[o * 384 + 3 * c + 1] + Wc1[o * 384 + 3 * c + 2];
    }
    if (t < 64) g_bc[t] = bc0[t] + bc1[t];
}

// ---------------- 2. adjacency + row sums ----------------
// softmax over 2 => sigmoid. With tau=0.5:
//   p = sigmoid((dl + n0 - n1)/tau) = g1^2 / (g1^2 + exp(-2*dl)*g0^2),
//   g = EPS - log(u + EPS).  (2 LG2 + 1 EX2 + 1 div instead of 4 logf + 1 expf)
__global__ void adj_kernel(const float2* __restrict__ lg, const float2* __restrict__ un) {
    int i = blockIdx.x, b = blockIdx.y;
    size_t base = (size_t)b * NN2 + (size_t)i * NND;
    float rsum = 0.f;
    for (int j = threadIdx.x; j < NND; j += 256) {
        float2 l = lg[base + j];
        float2 u = un[base + j];
        float g0 = EPSV - __logf(u.x + EPSV);
        float g1 = EPSV - __logf(u.y + EPSV);
        float E  = __expf(-2.0f * (l.x - l.y));
        float n  = g1 * g1;
        float p  = __fdividef(n, n + E * g0 * g0);
        g_adj[base + j] = p;
        rsum += p;
    }
    __shared__ float red[256];
    red[threadIdx.x] = rsum;
    __syncthreads();
    for (int s = 128; s > 0; s >>= 1) {
        if (threadIdx.x < s) red[threadIdx.x] += red[threadIdx.x + s];
        __syncthreads();
    }
    if (threadIdx.x == 0) g_rowsum[b * NND + i] = red[0];
}

// ---------------- 3. deterministic column sums ----------------
__global__ void colsum_kernel() {
    int j = blockIdx.x * 256 + threadIdx.x;   // gridDim.x = 4
    int b = blockIdx.y;
    int ch = blockIdx.z;                       // 4 chunks of 256 rows
    size_t base = (size_t)b * NN2 + (size_t)(ch * 256) * NND + j;
    float acc = 0.f;
    #pragma unroll 8
    for (int i = 0; i < 256; i++) acc += g_adj[base + (size_t)i * NND];
    g_colpart[ch * (BB * NND) + b * NND + j] = acc;
}

// ---------------- 4. scales (reference's column-sum quirk) ----------------
__global__ void scales_kernel() {
    int m = blockIdx.x * 256 + threadIdx.x;    // 16384
    float cs = g_colpart[m] + g_colpart[16384 + m] + g_colpart[2 * 16384 + m] + g_colpart[3 * 16384 + m];
    g_s0[m] = 1.0f / (cs + 1.0f);
    g_s1[m] = 1.0f / (g_rowsum[m] + 1.0f);
}

// ---------------- 5. X = [x | h] ----------------
__global__ void buildX_kernel(const float* __restrict__ inp, const float* __restrict__ hx) {
    int idx = blockIdx.x * 256 + threadIdx.x;  // 16384*128
    int m = idx >> 7, c = idx & 127;
    g_X[idx] = (c < 64) ? inp[m * 64 + c] : hx[m * 64 + (c - 64)];
}

// ---------------- 6. batched GEMM via tf32 tensor cores ----------------
// z=0: Y = adj @ X ; z=1: Y = adjT @ X.  CTA tile 128 x NC, K-chunk 32.
// Non-trans A staged [i][k] (row-major frag, ld 36); trans A staged [k][i]
// giving A'(i,k) at offset i + k*136 => col_major frag, ld 136.
template <int NC>
__global__ void __launch_bounds__(256)
adj_gemm_tc_kernel() {
    constexpr int WNF = NC / 32;               // 4 (NC=128) or 2 (NC=64)
    constexpr int LDA = 36;
    constexpr int LDT = 136;
    constexpr int LDB = NC + 8;                // 136 or 72
    const float* Xin = (NC == 128) ? g_X : g_Q;
    float* Y = (blockIdx.z == 0) ? ((NC == 128) ? g_G0 : g_H0)
                                 : ((NC == 128) ? g_G1 : g_H1);
    const bool trans = (blockIdx.z == 1);
    const int b  = blockIdx.y;
    const int i0 = blockIdx.x * 128;
    const float* Ab = g_adj + (size_t)b * NN2;
    const float* Xb = Xin + (size_t)b * NND * NC;

    __shared__ float AsBuf[128 * LDA];         // 4608 floats; trans view needs 32*136=4352
    __shared__ float Bs[32 * LDB];

    const int t    = threadIdx.x;
    const int warp = t >> 5;
    const int wy   = warp >> 1;                // 0..3 -> rows wy*32
    const int wx   = warp & 1;                 // 0..1 -> cols wx*(WNF*16)

    wmma::fragment<wmma::accumulator, 16, 16, 8, float> acc[2][WNF];
    #pragma unroll
    for (int mf = 0; mf < 2; mf++)
        #pragma unroll
        for (int nf = 0; nf < WNF; nf++) wmma::fill_fragment(acc[mf][nf], 0.0f);

    for (int k0 = 0; k0 < NND; k0 += 32) {
        // ---- stage A chunk ----
        if (!trans) {
            int i  = t >> 1;
            int c0 = (t & 1) * 16;
            const float4* src = reinterpret_cast<const float4*>(Ab + (size_t)(i0 + i) * NND + k0 + c0);
            float4* dst = reinterpret_cast<float4*>(&AsBuf[i * LDA + c0]);
            #pragma unroll
            for (int q = 0; q < 4; q++) dst[q] = src[q];
        } else {
            int k  = t >> 3;
            int c0 = (t & 7) * 16;
            const float4* src = reinterpret_cast<const float4*>(Ab + (size_t)(k0 + k) * NND + i0 + c0);
            float4* dst = reinterpret_cast<float4*>(&AsBuf[k * LDT + c0]);
            #pragma unroll
            for (int q = 0; q < 4; q++) dst[q] = src[q];
        }
        // ---- stage B chunk ----
        if (NC == 128) {
            int k  = t >> 3;
            int c0 = (t & 7) * 16;
            const float4* src = reinterpret_cast<const float4*>(Xb + (size_t)(k0 + k) * NC + c0);
            float4* dst = reinterpret_cast<float4*>(&Bs[k * LDB + c0]);
            #pragma unroll
            for (int q = 0; q < 4; q++) dst[q] = src[q];
        } else {
            int k  = t >> 3;
            int c0 = (t & 7) * 8;
            const float4* src = reinterpret_cast<const float4*>(Xb + (size_t)(k0 + k) * NC + c0);
            float4* dst = reinterpret_cast<float4*>(&Bs[k * LDB + c0]);
            #pragma unroll
            for (int q = 0; q < 2; q++) dst[q] = src[q];
        }
        __syncthreads();

        #pragma unroll
        for (int kk = 0; kk < 32; kk += 8) {
            wmma::fragment<wmma::matrix_b, 16, 16, 8, wmma::precision::tf32, wmma::row_major> bf[WNF];
            #pragma unroll
            for (int nf = 0; nf < WNF; nf++) {
                wmma::load_matrix_sync(bf[nf], &Bs[kk * LDB + wx * (WNF * 16) + nf * 16], LDB);
                #pragma unroll
                for (int e = 0; e < bf[nf].num_elements; e++)
                    bf[nf].x[e] = wmma::__float_to_tf32(bf[nf].x[e]);
            }
            if (!trans) {
                #pragma unroll
                for (int mf = 0; mf < 2; mf++) {
                    wmma::fragment<wmma::matrix_a, 16, 16, 8, wmma::precision::tf32, wmma::row_major> af;
                    wmma::load_matrix_sync(af, &AsBuf[(wy * 32 + mf * 16) * LDA + kk], LDA);
                    #pragma unroll
                    for (int e = 0; e < af.num_elements; e++)
                        af.x[e] = wmma::__float_to_tf32(af.x[e]);
                    #pragma unroll
                    for (int nf = 0; nf < WNF; nf++)
                        wmma::mma_sync(acc[mf][nf], af, bf[nf], acc[mf][nf]);
                }
            } else {
                #pragma unroll
                for (int mf = 0; mf < 2; mf++) {
                    wmma::fragment<wmma::matrix_a, 16, 16, 8, wmma::precision::tf32, wmma::col_major> af;
                    wmma::load_matrix_sync(af, &AsBuf[kk * LDT + (wy * 32 + mf * 16)], LDT);
                    #pragma unroll
                    for (int e = 0; e < af.num_elements; e++)
                        af.x[e] = wmma::__float_to_tf32(af.x[e]);
                    #pragma unroll
                    for (int nf = 0; nf < WNF; nf++)
                        wmma::mma_sync(acc[mf][nf], af, bf[nf], acc[mf][nf]);
                }
            }
        }
        __syncthreads();
    }

    #pragma unroll
    for (int mf = 0; mf < 2; mf++)
        #pragma unroll
        for (int nf = 0; nf < WNF; nf++) {
            float* dst = Y + ((size_t)b * NND + i0 + wy * 32 + mf * 16) * NC + wx * (WNF * 16) + nf * 16;
            wmma::store_matrix_sync(dst, acc[mf][nf], NC, wmma::mem_row_major);
        }
}

// ---------------- 7. diffusion-feature builds ----------------
__global__ void buildPhi1_kernel() {
    int idx = blockIdx.x * 256 + threadIdx.x;   // 16384*384
    int m = idx / 384;
    int k = idx - m * 384;
    float v;
    if (k < 128)      v = g_X[m * 128 + k];
    else if (k < 256) { int c = k - 128; v = g_s0[m] * (g_G0[m * 128 + c] + g_X[m * 128 + c]); }
    else              { int c = k - 256; v = g_s1[m] * (g_G1[m * 128 + c] + g_X[m * 128 + c]); }
    g_Phi[idx] = v;
}

__global__ void buildPhi2_kernel() {
    int idx = blockIdx.x * 256 + threadIdx.x;
    int m = idx / 384;
    int k = idx - m * 384;
    float v;
    if (k < 64)       v = g_X[m * 128 + k];
    else if (k < 128) v = g_Q[m * 64 + (k - 64)];
    else if (k < 192) { int c = k - 128; v = g_s0[m] * (g_G0[m * 128 + c] + g_X[m * 128 + c]); }
    else if (k < 256) { int c = k - 192; v = g_s0[m] * (g_H0[m * 64 + c] + g_Q[m * 64 + c]); }
    else if (k < 320) { int c = k - 256; v = g_s1[m] * (g_G1[m * 128 + c] + g_X[m * 128 + c]); }
    else              { int c = k - 320; v = g_s1[m] * (g_H1[m * 64 + c] + g_Q[m * 64 + c]); }
    g_Phi[idx] = v;
}

// ---------------- 8. FC GEMM (Phi @ W^T) with fused epilogues ----------------
template <int NC, int MODE>
__global__ void __launch_bounds__(256)
fc_gemm_kernel(const float* __restrict__ hx, float* __restrict__ out) {
    constexpr int TM  = (NC == 128) ? 8 : 4;
    constexpr int NTX = NC / 8;
    const float* Wt = (NC == 128) ? g_WT : g_WcT;
    const int m0 = blockIdx.x * 128;

    __shared__ float As[16][128];
    __shared__ float Ws[16][NC];

    const int t  = threadIdx.x;
    const int tx = t % NTX, ty = t / NTX;

    unsigned long long acc[TM][4];
    #pragma unroll
    for (int ii = 0; ii < TM; ii++)
        #pragma unroll
        for (int q = 0; q < 4; q++) acc[ii][q] = 0ULL;

    for (int k0 = 0; k0 < 384; k0 += 16) {
        {
            int iA = t >> 2;
            int kq = (t & 3) * 4;
            #pragma unroll
            for (int h = 0; h < 2; h++) {
                int ii = iA + h * 64;
                const float4 v = *reinterpret_cast<const float4*>(&g_Phi[(size_t)(m0 + ii) * 384 + k0 + kq]);
                As[kq + 0][ii] = v.x; As[kq + 1][ii] = v.y;
                As[kq + 2][ii] = v.z; As[kq + 3][ii] = v.w;
            }
        }
        if (NC == 128) {
            int j4 = (t & 31) * 4;
            int k  = t >> 5;
            #pragma unroll
            for (int h = 0; h < 2; h++) {
                int kk2 = k + h * 8;
                *reinterpret_cast<float4*>(&Ws[kk2][j4]) =
                    *reinterpret_cast<const float4*>(&Wt[(k0 + kk2) * NC + j4]);
            }
        } else {
            int j4 = (t & 15) * 4;
            int k  = t >> 4;
            *reinterpret_cast<float4*>(&Ws[k][j4]) =
                *reinterpret_cast<const float4*>(&Wt[(k0 + k) * NC + j4]);
        }
        __syncthreads();
        #pragma unroll
        for (int kk = 0; kk < 16; kk++) {
            float4 b0v = *reinterpret_cast<const float4*>(&Ws[kk][tx * 8]);
            float4 b1v = *reinterpret_cast<const float4*>(&Ws[kk][tx * 8 + 4]);
            unsigned long long bp0 = pk(b0v.x, b0v.y), bp1 = pk(b0v.z, b0v.w);
            unsigned long long bp2 = pk(b1v.x, b1v.y), bp3 = pk(b1v.z, b1v.w);
            #pragma unroll
            for (int ii = 0; ii < TM; ii++) {
                float a = As[kk][ty * TM + ii];
                unsigned long long ad = pk(a, a);
                acc[ii][0] = fma2(ad, bp0, acc[ii][0]);
                acc[ii][1] = fma2(ad, bp1, acc[ii][1]);
                acc[ii][2] = fma2(ad, bp2, acc[ii][2]);
                acc[ii][3] = fma2(ad, bp3, acc[ii][3]);
            }
        }
        __syncthreads();
    }
    #pragma unroll
    for (int ii = 0; ii < TM; ii++) {
        int m = m0 + ty * TM + ii;
        #pragma unroll
        for (int q = 0; q < 4; q++) {
            float2 v = unpk(acc[ii][q]);
            #pragma unroll
            for (int r = 0; r < 2; r++) {
                int o = tx * 8 + q * 2 + r;
                float val = (r == 0) ? v.x : v.y;
                if (MODE == 1) {
                    float y = val + g_bv[o];
                    float s = 1.0f / (1.0f + expf(-y));
                    if (o < 64) g_Q[m * 64 + o] = s * hx[m * 64 + o];       // r * h
                    else        g_Ubuf[m * 64 + (o - 64)] = s;              // u
                } else {
                    float y  = val + g_bc[o];
                    float cc = tanhf(y);
                    float u  = g_Ubuf[m * 64 + o];
                    float h  = hx[m * 64 + o];
                    out[m * 64 + o] = u * h + (1.0f - u) * cc;
                }
            }
        }
    }
}

// ---------------- launch ----------------
extern "C" void kernel_launch(void* const* d_in, const int* in_sizes, int n_in,
                              void* d_out, int out_size) {
    (void)in_sizes; (void)n_in; (void)out_size;
    const float* logits = (const float*)d_in[0];
    const float* unoise = (const float*)d_in[1];
    const float* inputs = (const float*)d_in[2];
    const float* hx     = (const float*)d_in[3];
    const float* W0  = (const float*)d_in[4];
    const float* b0  = (const float*)d_in[5];
    const float* W1  = (const float*)d_in[6];
    const float* b1  = (const float*)d_in[7];
    const float* Wc0 = (const float*)d_in[8];
    const float* bc0 = (const float*)d_in[9];
    const float* Wc1 = (const float*)d_in[10];
    const float* bc1 = (const float*)d_in[11];
    float* out = (float*)d_out;

    prep_weights_kernel<<<64, 256>>>(W0, b0, W1, b1, Wc0, bc0, Wc1, bc1);
    adj_kernel<<<dim3(NND, BB), 256>>>((const float2*)logits, (const float2*)unoise);
    colsum_kernel<<<dim3(4, BB, 4), 256>>>();
    scales_kernel<<<64, 256>>>();
    buildX_kernel<<<(BB * NND * 128) / 256, 256>>>(inputs, hx);
    adj_gemm_tc_kernel<128><<<dim3(8, BB, 2), 256>>>();         // G0 = adj@X, G1 = adjT@X
    buildPhi1_kernel<<<(BB * NND * 384) / 256, 256>>>();
    fc_gemm_kernel<128, 1><<<dim3(128), 256>>>(hx, out);        // value, r*h, u
    adj_gemm_tc_kernel<64><<<dim3(8, BB, 2), 256>>>();          // H0 = adj@Q, H1 = adjT@Q
    buildPhi2_kernel<<<(BB * NND * 384) / 256, 256>>>();
    fc_gemm_kernel<64, 2><<<dim3(128), 256>>>(hx, out);         // c, new_state
}

// round 10
// speedup vs baseline: 1.4943x; 1.2530x over previous
#include <cuda_runtime.h>
#include <mma.h>
using namespace nvcuda;

// Problem constants
#define BB 16
#define NND 1024
#define UU 64
#define NN2 (NND*NND)
#define TAUV 0.5f
#define EPSV 1e-10f

// ---------------- scratch (device globals; no allocations allowed) ----------------
__device__ float g_adj[(size_t)BB*NND*NND];   // 64 MB
__device__ float g_rowsum[BB*NND];
__device__ float g_colpart[4*BB*NND];
__device__ float g_s0[BB*NND];
__device__ float g_s1[BB*NND];
__device__ float g_X[BB*NND*128];             // [x | h]
__device__ float g_G0[BB*NND*128];            // adj  @ X
__device__ float g_G1[BB*NND*128];            // adjT @ X
__device__ float g_Q[BB*NND*64];              // r * h
__device__ float g_Ubuf[BB*NND*64];           // u gate
__device__ float g_H0[BB*NND*64];             // adj  @ Q
__device__ float g_H1[BB*NND*64];             // adjT @ Q
__device__ float g_Phi[BB*NND*384];           // diffusion features (reused both phases)
__device__ float g_WT[384*128];               // [Wx0+Wx1 | W0a | W1a] transposed (k-major)
__device__ float g_bv[128];
__device__ float g_WcT[384*64];
__device__ float g_bc[64];

// ---------------- packed f32x2 helpers (fc_gemm path) ----------------
__device__ __forceinline__ unsigned long long fma2(unsigned long long a,
                                                   unsigned long long b,
                                                   unsigned long long c) {
    unsigned long long d;
    asm("fma.rn.f32x2 %0, %1, %2, %3;" : "=l"(d) : "l"(a), "l"(b), "l"(c));
    return d;
}
__device__ __forceinline__ unsigned long long pk(float lo, float hi) {
    unsigned long long r;
    asm("mov.b64 %0, {%1, %2};" : "=l"(r) : "f"(lo), "f"(hi));
    return r;
}
__device__ __forceinline__ float2 unpk(unsigned long long v) {
    float2 r;
    asm("mov.b64 {%0, %1}, %2;" : "=f"(r.x), "=f"(r.y) : "l"(v));
    return r;
}

// ---------------- cp.async helpers ----------------
__device__ __forceinline__ void cpa16(float* smem_dst, const float* gmem_src) {
    unsigned saddr = (unsigned)__cvta_generic_to_shared(smem_dst);
    asm volatile("cp.async.cg.shared.global [%0], [%1], 16;\n" :: "r"(saddr), "l"(gmem_src));
}
__device__ __forceinline__ void cpa_commit() {
    asm volatile("cp.async.commit_group;\n");
}
template <int N>
__device__ __forceinline__ void cpa_wait() {
    asm volatile("cp.async.wait_group %0;\n" :: "n"(N));
}

// ---------------- 1. weight preprocessing ----------------
// _diffusion stacks [x, Ax, Ax]  =>  effective weights:
//   Wx[o,c] = W[o,3c],  Wa[o,c] = W[o,3c+1] + W[o,3c+2]
__global__ void prep_weights_kernel(const float* __restrict__ W0, const float* __restrict__ b0,
                                    const float* __restrict__ W1, const float* __restrict__ b1,
                                    const float* __restrict__ Wc0, const float* __restrict__ bc0,
                                    const float* __restrict__ Wc1, const float* __restrict__ bc1) {
    int t = blockIdx.x * blockDim.x + threadIdx.x;
    if (t < 128 * 128) {
        int c = t >> 7, o = t & 127;
        g_WT[c * 128 + o]         = W0[o * 384 + 3 * c]     + W1[o * 384 + 3 * c];
        g_WT[(128 + c) * 128 + o] = W0[o * 384 + 3 * c + 1] + W0[o * 384 + 3 * c + 2];
        g_WT[(256 + c) * 128 + o] = W1[o * 384 + 3 * c + 1] + W1[o * 384 + 3 * c + 2];
    }
    if (t < 128) g_bv[t] = b0[t] + b1[t];
    if (t < 128 * 64) {
        int c = t >> 6, o = t & 63;
        g_WcT[c * 64 + o]         = Wc0[o * 384 + 3 * c]     + Wc1[o * 384 + 3 * c];
        g_WcT[(128 + c) * 64 + o] = Wc0[o * 384 + 3 * c + 1] + Wc0[o * 384 + 3 * c + 2];
        g_WcT[(256 + c) * 64 + o] = Wc1[o * 384 + 3 * c + 1] + Wc1[o * 384 + 3 * c + 2];
    }
    if (t < 64) g_bc[t] = bc0[t] + bc1[t];
}

// ---------------- 2. adjacency + row sums ----------------
// softmax over 2 => sigmoid. With tau=0.5:
//   p = g1^2 / (g1^2 + exp(-2*dl)*g0^2),  g = EPS - log(u + EPS)
__global__ void adj_kernel(const float2* __restrict__ lg, const float2* __restrict__ un) {
    int i = blockIdx.x, b = blockIdx.y;
    size_t base = (size_t)b * NN2 + (size_t)i * NND;
    float rsum = 0.f;
    for (int j = threadIdx.x; j < NND; j += 256) {
        float2 l = lg[base + j];
        float2 u = un[base + j];
        float g0 = EPSV - __logf(u.x + EPSV);
        float g1 = EPSV - __logf(u.y + EPSV);
        float E  = __expf(-2.0f * (l.x - l.y));
        float n  = g1 * g1;
        float p  = __fdividef(n, n + E * g0 * g0);
        g_adj[base + j] = p;
        rsum += p;
    }
    __shared__ float red[256];
    red[threadIdx.x] = rsum;
    __syncthreads();
    for (int s = 128; s > 0; s >>= 1) {
        if (threadIdx.x < s) red[threadIdx.x] += red[threadIdx.x + s];
        __syncthreads();
    }
    if (threadIdx.x == 0) g_rowsum[b * NND + i] = red[0];
}

// ---------------- 3. deterministic column sums ----------------
__global__ void colsum_kernel() {
    int j = blockIdx.x * 256 + threadIdx.x;   // gridDim.x = 4
    int b = blockIdx.y;
    int ch = blockIdx.z;                       // 4 chunks of 256 rows
    size_t base = (size_t)b * NN2 + (size_t)(ch * 256) * NND + j;
    float acc = 0.f;
    #pragma unroll 8
    for (int i = 0; i < 256; i++) acc += g_adj[base + (size_t)i * NND];
    g_colpart[ch * (BB * NND) + b * NND + j] = acc;
}

// ---------------- 4. scales (reference's column-sum quirk) ----------------
__global__ void scales_kernel() {
    int m = blockIdx.x * 256 + threadIdx.x;    // 16384
    float cs = g_colpart[m] + g_colpart[16384 + m] + g_colpart[2 * 16384 + m] + g_colpart[3 * 16384 + m];
    g_s0[m] = 1.0f / (cs + 1.0f);
    g_s1[m] = 1.0f / (g_rowsum[m] + 1.0f);
}

// ---------------- 5. X = [x | h] ----------------
__global__ void buildX_kernel(const float* __restrict__ inp, const float* __restrict__ hx) {
    int idx = blockIdx.x * 256 + threadIdx.x;  // 16384*128
    int m = idx >> 7, c = idx & 127;
    g_X[idx] = (c < 64) ? inp[m * 64 + c] : hx[m * 64 + (c - 64)];
}

// ---------------- 6. batched GEMM via tf32 tensor cores (cp.async pipelined) ----------------
// z=0: Y = adj @ X ; z=1: Y = adjT @ X.  CTA tile 128 x NC, K-chunk 16, double-buffered.
// No explicit f32->tf32 cvt: HMMA tf32 uses only the high 19 bits (truncation), error
// bounded by ~1 extra ulp vs RN — well inside budget (measured rel_err 7.7e-6 with RN).
template <int NC>
__global__ void __launch_bounds__(256)
adj_gemm_tc_kernel() {
    constexpr int WNF = NC / 32;               // 4 (NC=128) or 2 (NC=64)
    constexpr int LDA = 20;                    // non-trans: 128 rows x 16 floats (+4 pad)
    constexpr int LDT = 136;                   // trans: 16 rows(k) x 128 floats (+8 pad)
    constexpr int ASZ = 128 * LDA;             // 2560 >= 16*136=2176
    constexpr int LDB = NC + 8;                // 136 or 72
    constexpr int BSZ = 16 * LDB;
    const float* Xin = (NC == 128) ? g_X : g_Q;
    float* Y = (blockIdx.z == 0) ? ((NC == 128) ? g_G0 : g_H0)
                                 : ((NC == 128) ? g_G1 : g_H1);
    const bool trans = (blockIdx.z == 1);
    const int b  = blockIdx.y;
    const int i0 = blockIdx.x * 128;
    const float* Ab = g_adj + (size_t)b * NN2;
    const float* Xb = Xin + (size_t)b * NND * NC;

    __shared__ float As[2][ASZ];
    __shared__ float Bs[2][BSZ];

    const int t    = threadIdx.x;
    const int warp = t >> 5;
    const int wy   = warp >> 1;                // 0..3 -> rows wy*32
    const int wx   = warp & 1;                 // 0..1 -> cols wx*(WNF*16)

    wmma::fragment<wmma::accumulator, 16, 16, 8, float> acc[2][WNF];
    #pragma unroll
    for (int mf = 0; mf < 2; mf++)
        #pragma unroll
        for (int nf = 0; nf < WNF; nf++) wmma::fill_fragment(acc[mf][nf], 0.0f);

    // ---- async staging of one K-chunk (16) into buffer bf ----
    auto stage = [&](int bf, int k0) {
        if (!trans) {
            // A: 128 x 16 floats = 512 16B-chunks, 2 per thread
            #pragma unroll
            for (int q = 0; q < 2; q++) {
                int c  = t + 256 * q;
                int i  = c >> 2;
                int o4 = (c & 3) * 4;
                cpa16(&As[bf][i * LDA + o4], Ab + (size_t)(i0 + i) * NND + k0 + o4);
            }
        } else {
            // A': 16 rows(k) x 128 floats = 512 chunks
            #pragma unroll
            for (int q = 0; q < 2; q++) {
                int c  = t + 256 * q;
                int k  = c >> 5;
                int j4 = (c & 31) * 4;
                cpa16(&As[bf][k * LDT + j4], Ab + (size_t)(k0 + k) * NND + i0 + j4);
            }
        }
        if (NC == 128) {
            #pragma unroll
            for (int q = 0; q < 2; q++) {
                int c  = t + 256 * q;
                int k  = c >> 5;
                int j4 = (c & 31) * 4;
                cpa16(&Bs[bf][k * LDB + j4], Xb + (size_t)(k0 + k) * NC + j4);
            }
        } else {
            int k  = t >> 4;
            int j4 = (t & 15) * 4;
            cpa16(&Bs[bf][k * LDB + j4], Xb + (size_t)(k0 + k) * NC + j4);
        }
    };

    stage(0, 0);
    cpa_commit();
    int buf = 0;

    for (int k0 = 0; k0 < NND; k0 += 16) {
        if (k0 + 16 < NND) {
            stage(buf ^ 1, k0 + 16);
            cpa_commit();
            cpa_wait<1>();
        } else {
            cpa_wait<0>();
        }
        __syncthreads();

        #pragma unroll
        for (int kk = 0; kk < 16; kk += 8) {
            wmma::fragment<wmma::matrix_b, 16, 16, 8, wmma::precision::tf32, wmma::row_major> bf_[WNF];
            #pragma unroll
            for (int nf = 0; nf < WNF; nf++)
                wmma::load_matrix_sync(bf_[nf], &Bs[buf][kk * LDB + wx * (WNF * 16) + nf * 16], LDB);
            if (!trans) {
                #pragma unroll
                for (int mf = 0; mf < 2; mf++) {
                    wmma::fragment<wmma::matrix_a, 16, 16, 8, wmma::precision::tf32, wmma::row_major> af;
                    wmma::load_matrix_sync(af, &As[buf][(wy * 32 + mf * 16) * LDA + kk], LDA);
                    #pragma unroll
                    for (int nf = 0; nf < WNF; nf++)
                        wmma::mma_sync(acc[mf][nf], af, bf_[nf], acc[mf][nf]);
                }
            } else {
                #pragma unroll
                for (int mf = 0; mf < 2; mf++) {
                    wmma::fragment<wmma::matrix_a, 16, 16, 8, wmma::precision::tf32, wmma::col_major> af;
                    wmma::load_matrix_sync(af, &As[buf][kk * LDT + (wy * 32 + mf * 16)], LDT);
                    #pragma unroll
                    for (int nf = 0; nf < WNF; nf++)
                        wmma::mma_sync(acc[mf][nf], af, bf_[nf], acc[mf][nf]);
                }
            }
        }
        __syncthreads();
        buf ^= 1;
    }

    #pragma unroll
    for (int mf = 0; mf < 2; mf++)
        #pragma unroll
        for (int nf = 0; nf < WNF; nf++) {
            float* dst = Y + ((size_t)b * NND + i0 + wy * 32 + mf * 16) * NC + wx * (WNF * 16) + nf * 16;
            wmma::store_matrix_sync(dst, acc[mf][nf], NC, wmma::mem_row_major);
        }
}

// ---------------- 7. diffusion-feature builds ----------------
__global__ void buildPhi1_kernel() {
    int idx = blockIdx.x * 256 + threadIdx.x;   // 16384*384
    int m = idx / 384;
    int k = idx - m * 384;
    float v;
    if (k < 128)      v = g_X[m * 128 + k];
    else if (k < 256) { int c = k - 128; v = g_s0[m] * (g_G0[m * 128 + c] + g_X[m * 128 + c]); }
    else              { int c = k - 256; v = g_s1[m] * (g_G1[m * 128 + c] + g_X[m * 128 + c]); }
    g_Phi[idx] = v;
}

__global__ void buildPhi2_kernel() {
    int idx = blockIdx.x * 256 + threadIdx.x;
    int m = idx / 384;
    int k = idx - m * 384;
    float v;
    if (k < 64)       v = g_X[m * 128 + k];
    else if (k < 128) v = g_Q[m * 64 + (k - 64)];
    else if (k < 192) { int c = k - 128; v = g_s0[m] * (g_G0[m * 128 + c] + g_X[m * 128 + c]); }
    else if (k < 256) { int c = k - 192; v = g_s0[m] * (g_H0[m * 64 + c] + g_Q[m * 64 + c]); }
    else if (k < 320) { int c = k - 256; v = g_s1[m] * (g_G1[m * 128 + c] + g_X[m * 128 + c]); }
    else              { int c = k - 320; v = g_s1[m] * (g_H1[m * 64 + c] + g_Q[m * 64 + c]); }
    g_Phi[idx] = v;
}

// ---------------- 8. FC GEMM (Phi @ W^T), register-prefetch pipelined, fused epilogues ----------------
template <int NC, int MODE>
__global__ void __launch_bounds__(256)
fc_gemm_kernel(const float* __restrict__ hx, float* __restrict__ out) {
    constexpr int TM  = (NC == 128) ? 8 : 4;
    constexpr int NTX = NC / 8;
    const float* Wt = (NC == 128) ? g_WT : g_WcT;
    const int m0 = blockIdx.x * 128;

    __shared__ float As[16][128];
    __shared__ float Ws[16][NC];

    const int t  = threadIdx.x;
    const int tx = t % NTX, ty = t / NTX;

    unsigned long long acc[TM][4];
    #pragma unroll
    for (int ii = 0; ii < TM; ii++)
        #pragma unroll
        for (int q = 0; q < 4; q++) acc[ii][q] = 0ULL;

    // staging indices
    const int iA = t >> 2;
    const int kq = (t & 3) * 4;
    const int jw = (NC == 128) ? (t & 31) * 4 : (t & 15) * 4;
    const int kw = (NC == 128) ? (t >> 5) : (t >> 4);

    // prefetch k0 = 0
    float4 ra0 = *reinterpret_cast<const float4*>(&g_Phi[(size_t)(m0 + iA) * 384 + kq]);
    float4 ra1 = *reinterpret_cast<const float4*>(&g_Phi[(size_t)(m0 + iA + 64) * 384 + kq]);
    float4 rw0 = *reinterpret_cast<const float4*>(&Wt[kw * NC + jw]);
    float4 rw1;
    if (NC == 128) rw1 = *reinterpret_cast<const float4*>(&Wt[(kw + 8) * NC + jw]);

    for (int k0 = 0; k0 < 384; k0 += 16) {
        // commit staged regs to smem
        As[kq + 0][iA] = ra0.x; As[kq + 1][iA] = ra0.y;
        As[kq + 2][iA] = ra0.z; As[kq + 3][iA] = ra0.w;
        As[kq + 0][iA + 64] = ra1.x; As[kq + 1][iA + 64] = ra1.y;
        As[kq + 2][iA + 64] = ra1.z; As[kq + 3][iA + 64] = ra1.w;
        *reinterpret_cast<float4*>(&Ws[kw][jw]) = rw0;
        if (NC == 128) *reinterpret_cast<float4*>(&Ws[kw + 8][jw]) = rw1;
        __syncthreads();

        if (k0 + 16 < 384) {
            ra0 = *reinterpret_cast<const float4*>(&g_Phi[(size_t)(m0 + iA) * 384 + k0 + 16 + kq]);
            ra1 = *reinterpret_cast<const float4*>(&g_Phi[(size_t)(m0 + iA + 64) * 384 + k0 + 16 + kq]);
            rw0 = *reinterpret_cast<const float4*>(&Wt[(k0 + 16 + kw) * NC + jw]);
            if (NC == 128) rw1 = *reinterpret_cast<const float4*>(&Wt[(k0 + 16 + kw + 8) * NC + jw]);
        }

        #pragma unroll
        for (int kk = 0; kk < 16; kk++) {
            float4 b0v = *reinterpret_cast<const float4*>(&Ws[kk][tx * 8]);
            float4 b1v = *reinterpret_cast<const float4*>(&Ws[kk][tx * 8 + 4]);
            unsigned long long bp0 = pk(b0v.x, b0v.y), bp1 = pk(b0v.z, b0v.w);
            unsigned long long bp2 = pk(b1v.x, b1v.y), bp3 = pk(b1v.z, b1v.w);
            #pragma unroll
            for (int ii = 0; ii < TM; ii++) {
                float a = As[kk][ty * TM + ii];
                unsigned long long ad = pk(a, a);
                acc[ii][0] = fma2(ad, bp0, acc[ii][0]);
                acc[ii][1] = fma2(ad, bp1, acc[ii][1]);
                acc[ii][2] = fma2(ad, bp2, acc[ii][2]);
                acc[ii][3] = fma2(ad, bp3, acc[ii][3]);
            }
        }
        __syncthreads();
    }
    #pragma unroll
    for (int ii = 0; ii < TM; ii++) {
        int m = m0 + ty * TM + ii;
        #pragma unroll
        for (int q = 0; q < 4; q++) {
            float2 v = unpk(acc[ii][q]);
            #pragma unroll
            for (int r = 0; r < 2; r++) {
                int o = tx * 8 + q * 2 + r;
                float val = (r == 0) ? v.x : v.y;
                if (MODE == 1) {
                    float y = val + g_bv[o];
                    float s = 1.0f / (1.0f + expf(-y));
                    if (o < 64) g_Q[m * 64 + o] = s * hx[m * 64 + o];       // r * h
                    else        g_Ubuf[m * 64 + (o - 64)] = s;              // u
                } else {
                    float y  = val + g_bc[o];
                    float cc = tanhf(y);
                    float u  = g_Ubuf[m * 64 + o];
                    float h  = hx[m * 64 + o];
                    out[m * 64 + o] = u * h + (1.0f - u) * cc;
                }
            }
        }
    }
}

// ---------------- launch ----------------
extern "C" void kernel_launch(void* const* d_in, const int* in_sizes, int n_in,
                              void* d_out, int out_size) {
    (void)in_sizes; (void)n_in; (void)out_size;
    const float* logits = (const float*)d_in[0];
    const float* unoise = (const float*)d_in[1];
    const float* inputs = (const float*)d_in[2];
    const float* hx     = (const float*)d_in[3];
    const float* W0  = (const float*)d_in[4];
    const float* b0  = (const float*)d_in[5];
    const float* W1  = (const float*)d_in[6];
    const float* b1  = (const float*)d_in[7];
    const float* Wc0 = (const float*)d_in[8];
    const float* bc0 = (const float*)d_in[9];
    const float* Wc1 = (const float*)d_in[10];
    const float* bc1 = (const float*)d_in[11];
    float* out = (float*)d_out;

    prep_weights_kernel<<<64, 256>>>(W0, b0, W1, b1, Wc0, bc0, Wc1, bc1);
    adj_kernel<<<dim3(NND, BB), 256>>>((const float2*)logits, (const float2*)unoise);
    colsum_kernel<<<dim3(4, BB, 4), 256>>>();
    scales_kernel<<<64, 256>>>();
    buildX_kernel<<<(BB * NND * 128) / 256, 256>>>(inputs, hx);
    adj_gemm_tc_kernel<128><<<dim3(8, BB, 2), 256>>>();         // G0 = adj@X, G1 = adjT@X
    buildPhi1_kernel<<<(BB * NND * 384) / 256, 256>>>();
    fc_gemm_kernel<128, 1><<<dim3(128), 256>>>(hx, out);        // value, r*h, u
    adj_gemm_tc_kernel<64><<<dim3(8, BB, 2), 256>>>();          // H0 = adj@Q, H1 = adjT@Q
    buildPhi2_kernel<<<(BB * NND * 384) / 256, 256>>>();
    fc_gemm_kernel<64, 2><<<dim3(128), 256>>>(hx, out);         // c, new_state
}